// round 1
// baseline (speedup 1.0000x reference)
#include <cuda_runtime.h>
#include <math.h>

#define Bdim 16
#define Sdim 1024
#define Ddim 512
#define Hdim 8
#define DHdim 64

// ---------------- scratch (static device globals; no runtime alloc) ----------
__device__ float g_conv [Bdim*Ddim*Sdim];           // conv + pe (pre-gelu), residual source
__device__ float g_n1   [Bdim*Ddim*Sdim];           // after LN1
__device__ float g_dense[Bdim*Ddim*Sdim];           // dense + ts_emb
__device__ float g_q    [Bdim*Ddim*Sdim];           // (b, h*64+c, s)
__device__ float g_k    [Bdim*Ddim*Sdim];           // (b, h*64+c, s)
__device__ float g_vt   [Bdim*Hdim*Sdim*DHdim];     // (b, h, s, c)
__device__ float g_sc   [(size_t)Bdim*Hdim*Sdim*Sdim]; // scT[bh][j][i]
__device__ float g_rinv [Bdim*Hdim*Sdim];           // 1/rowsum per (bh, j)
__device__ float g_attnT[Bdim*Hdim*Sdim*DHdim];     // (b, h, j, c)

// ---------------- small helpers ----------------
__device__ __forceinline__ float warp_sum(float v){
    #pragma unroll
    for(int o=16;o;o>>=1) v += __shfl_xor_sync(0xffffffffu, v, o);
    return v;
}
__device__ __forceinline__ float warp_max(float v){
    #pragma unroll
    for(int o=16;o;o>>=1) v = fmaxf(v, __shfl_xor_sync(0xffffffffu, v, o));
    return v;
}

#define GEMM_FMA16()                                                          \
    _Pragma("unroll")                                                         \
    for(int kk=0;kk<16;kk++){                                                 \
        float4 a = *(const float4*)&As[kk][ty*4];                             \
        float4 v = *(const float4*)&Bs[kk][tx*4];                             \
        acc[0][0]+=a.x*v.x; acc[0][1]+=a.x*v.y; acc[0][2]+=a.x*v.z; acc[0][3]+=a.x*v.w; \
        acc[1][0]+=a.y*v.x; acc[1][1]+=a.y*v.y; acc[1][2]+=a.y*v.z; acc[1][3]+=a.y*v.w; \
        acc[2][0]+=a.z*v.x; acc[2][1]+=a.z*v.y; acc[2][2]+=a.z*v.z; acc[2][3]+=a.z*v.w; \
        acc[3][0]+=a.w*v.x; acc[3][1]+=a.w*v.y; acc[3][2]+=a.w*v.z; acc[3][3]+=a.w*v.w; \
    }

// ============ Kernel 1: conv(patch) + pe + [store conv] + gelu + LN1(dim D) ==
// grid (S/16, B), block 512. smem transpose tile for coalesced (B,D,S) stores.
__global__ void k_front(const float* __restrict__ ts, const float* __restrict__ cw,
                        const float* __restrict__ cb, const float* __restrict__ pe,
                        const float* __restrict__ g1, const float* __restrict__ b1)
{
    __shared__ float sm[16][513];
    int b = blockIdx.y, s0 = blockIdx.x*16;
    int tid = threadIdx.x;
    int d = tid;
    float w0=cw[d*4+0], w1=cw[d*4+1], w2=cw[d*4+2], w3=cw[d*4+3];
    float bias = cb[d];
    const float* tsb = ts + b*4096;
    #pragma unroll
    for(int sl=0; sl<16; ++sl){
        int s = s0+sl;
        float v = bias + pe[s*Ddim + d]
                + tsb[s*4+0]*w0 + tsb[s*4+1]*w1 + tsb[s*4+2]*w2 + tsb[s*4+3]*w3;
        sm[sl][d] = v;
    }
    __syncthreads();
    float* convp = g_conv + (size_t)b*Ddim*Sdim;
    #pragma unroll
    for(int it=0; it<16; ++it){
        int idx = it*512 + tid; int sl = idx & 15, dd = idx >> 4;
        convp[(size_t)dd*Sdim + s0 + sl] = sm[sl][dd];
    }
    __syncthreads();
    #pragma unroll
    for(int sl=0; sl<16; ++sl){
        float x = sm[sl][d];
        sm[sl][d] = 0.5f*x*(1.0f + erff(x*0.70710678118654752f));
    }
    __syncthreads();
    int wrp = tid>>5, lane = tid&31;
    {
        float sum=0.f, sq=0.f;
        #pragma unroll
        for(int k=0;k<16;k++){ float x = sm[wrp][lane + k*32]; sum+=x; sq+=x*x; }
        sum = warp_sum(sum); sq = warp_sum(sq);
        float mean = sum*(1.0f/512.0f);
        float var  = (sq - 512.0f*mean*mean)*(1.0f/511.0f);
        float inv  = rsqrtf(var + 1e-5f);
        float gg = g1[s0+wrp], bb = b1[s0+wrp];
        #pragma unroll
        for(int k=0;k<16;k++){
            int dd = lane + k*32;
            sm[wrp][dd] = (sm[wrp][dd]-mean)*inv*gg + bb;
        }
    }
    __syncthreads();
    float* n1p = g_n1 + (size_t)b*Ddim*Sdim;
    #pragma unroll
    for(int it=0; it<16; ++it){
        int idx = it*512 + tid; int sl = idx & 15, dd = idx >> 4;
        n1p[(size_t)dd*Sdim + s0 + sl] = sm[sl][dd];
    }
}

// ============ Kernel 2: dense = M @ n1 + ts_emb[te[b]]  (per batch) =========
// grid (S/64, D/64, B), block 256.
__global__ void gemm_dense(const float* __restrict__ M, const float* __restrict__ tsemb,
                           const int* __restrict__ te)
{
    __shared__ float As[16][68];
    __shared__ float Bs[16][68];
    int b = blockIdx.z;
    int m0 = blockIdx.y*64, n0 = blockIdx.x*64;
    const float* Bm = g_n1 + (size_t)b*Ddim*Sdim;
    float* C = g_dense + (size_t)b*Ddim*Sdim;
    int tid = threadIdx.x;
    int tx = tid & 15, ty = tid >> 4;
    int am = tid >> 2, ak = (tid & 3)*4;
    int bk = tid >> 4, bn = (tid & 15)*4;
    float acc[4][4] = {};
    for(int k0=0;k0<512;k0+=16){
        float4 av = *(const float4*)&M[(size_t)(m0+am)*512 + k0+ak];
        float4 bv = *(const float4*)&Bm[(size_t)(k0+bk)*Sdim + n0+bn];
        As[ak+0][am]=av.x; As[ak+1][am]=av.y; As[ak+2][am]=av.z; As[ak+3][am]=av.w;
        *(float4*)&Bs[bk][bn] = bv;
        __syncthreads();
        GEMM_FMA16();
        __syncthreads();
    }
    int teb = te[b];
    const float* emb = tsemb + (size_t)teb*512;
    #pragma unroll
    for(int i=0;i<4;i++){
        int row = m0 + ty*4 + i;
        float e = emb[row];
        float4 r; r.x=acc[i][0]+e; r.y=acc[i][1]+e; r.z=acc[i][2]+e; r.w=acc[i][3]+e;
        *(float4*)&C[(size_t)row*Sdim + n0+tx*4] = r;
    }
}

// ============ Kernel 3: Q/K/V = W{q,k,v} @ dense  ============================
// grid (S/64, 1536/64=24, B). sel picks which W / output.
__global__ void gemm_qkv(const float* __restrict__ Wq, const float* __restrict__ Wk,
                         const float* __restrict__ Wv)
{
    __shared__ float As[16][68];
    __shared__ float Bs[16][68];
    int b = blockIdx.z;
    int gm = blockIdx.y*64;
    int sel = gm >> 9;
    int m0 = gm & 511, n0 = blockIdx.x*64;
    const float* A = (sel==0) ? Wq : ((sel==1) ? Wk : Wv);
    const float* Bm = g_dense + (size_t)b*Ddim*Sdim;
    int tid = threadIdx.x;
    int tx = tid & 15, ty = tid >> 4;
    int am = tid >> 2, ak = (tid & 3)*4;
    int bk = tid >> 4, bn = (tid & 15)*4;
    float acc[4][4] = {};
    for(int k0=0;k0<512;k0+=16){
        float4 av = *(const float4*)&A[(size_t)(m0+am)*512 + k0+ak];
        float4 bv = *(const float4*)&Bm[(size_t)(k0+bk)*Sdim + n0+bn];
        As[ak+0][am]=av.x; As[ak+1][am]=av.y; As[ak+2][am]=av.z; As[ak+3][am]=av.w;
        *(float4*)&Bs[bk][bn] = bv;
        __syncthreads();
        GEMM_FMA16();
        __syncthreads();
    }
    if(sel < 2){
        float* C = (sel==0 ? g_q : g_k) + (size_t)b*Ddim*Sdim;
        #pragma unroll
        for(int i=0;i<4;i++){
            int row = m0 + ty*4 + i;
            *(float4*)&C[(size_t)row*Sdim + n0+tx*4] =
                make_float4(acc[i][0],acc[i][1],acc[i][2],acc[i][3]);
        }
    } else {
        #pragma unroll
        for(int i=0;i<4;i++){
            int row = m0 + ty*4 + i;
            size_t basev = (((size_t)b*Hdim + (row>>6))*Sdim)*DHdim + (row&63);
            #pragma unroll
            for(int j=0;j<4;j++){
                int col = n0 + tx*4 + j;
                g_vt[basev + (size_t)col*DHdim] = acc[i][j];
            }
        }
    }
}

// ============ Kernel 4: scT[j,i] = (Q_i . K_j)/8  (causal tiles only) ========
// grid (S/64 i, S/64 j, B*H).
__global__ void gemm_sc()
{
    __shared__ float As[16][68];
    __shared__ float Bs[16][68];
    int bh = blockIdx.z;
    int m0 = blockIdx.y*64;   // j
    int n0 = blockIdx.x*64;   // i
    if(n0 > m0+63) return;    // whole tile has i>j
    const float* K = g_k + (size_t)bh*DHdim*Sdim;
    const float* Q = g_q + (size_t)bh*DHdim*Sdim;
    int tid = threadIdx.x;
    int tx = tid & 15, ty = tid >> 4;
    int ck = tid >> 4, jn = (tid & 15)*4;
    float acc[4][4] = {};
    #pragma unroll
    for(int k0=0;k0<64;k0+=16){
        float4 av = *(const float4*)&K[(size_t)(k0+ck)*Sdim + m0+jn]; // A[m=j][k=c]
        float4 bv = *(const float4*)&Q[(size_t)(k0+ck)*Sdim + n0+jn]; // B[k=c][n=i]
        *(float4*)&As[ck][jn] = av;
        *(float4*)&Bs[ck][jn] = bv;
        __syncthreads();
        GEMM_FMA16();
        __syncthreads();
    }
    float* C = g_sc + ((size_t)bh*Sdim + m0)*Sdim;
    #pragma unroll
    for(int i=0;i<4;i++){
        int row = ty*4 + i;
        *(float4*)&C[(size_t)row*Sdim + n0+tx*4] =
            make_float4(acc[i][0]*0.125f, acc[i][1]*0.125f, acc[i][2]*0.125f, acc[i][3]*0.125f);
    }
}

// ============ Kernel 5: softmax over i<=j, store exp; 1/sum to g_rinv ========
// grid (S, B*H), block 256.
__global__ void k_softmax()
{
    int j = blockIdx.x, bh = blockIdx.y;
    float* row = g_sc + ((size_t)bh*Sdim + j)*Sdim;
    int n = j+1;
    int tid = threadIdx.x, lane = tid&31, wrp = tid>>5;
    __shared__ float red[8];
    float m = -1e30f;
    for(int i=tid;i<n;i+=256) m = fmaxf(m, row[i]);
    m = warp_max(m);
    if(lane==0) red[wrp]=m;
    __syncthreads();
    if(wrp==0){
        float t = (lane<8) ? red[lane] : -1e30f;
        t = warp_max(t);
        if(lane==0) red[0]=t;
    }
    __syncthreads();
    float M = red[0];
    __syncthreads();
    float s = 0.f;
    for(int i=tid;i<n;i+=256){
        float e = __expf(row[i]-M);
        row[i] = e;
        s += e;
    }
    s = warp_sum(s);
    if(lane==0) red[wrp]=s;
    __syncthreads();
    if(wrp==0){
        float t = (lane<8) ? red[lane] : 0.f;
        t = warp_sum(t);
        if(lane==0) g_rinv[(size_t)bh*Sdim + j] = 1.0f/t;
    }
}

// ============ Kernel 6: attnT[j,c] = (sum_{i<=j} p[j,i] Vt[i,c]) * rinv[j] ===
// grid (1, S/64, B*H).
__global__ void gemm_av()
{
    __shared__ float As[16][68];
    __shared__ float Bs[16][68];
    int bh = blockIdx.z;
    int m0 = blockIdx.y*64;  // j tile
    const float* A  = g_sc + (size_t)bh*Sdim*Sdim;  // p, lda=S
    const float* Bv = g_vt + (size_t)bh*Sdim*DHdim; // (S x 64)
    int tid = threadIdx.x;
    int tx = tid & 15, ty = tid >> 4;
    int am = tid >> 2, ak = (tid & 3)*4;
    int bk = tid >> 4, bn = (tid & 15)*4;
    float acc[4][4] = {};
    int kmax = m0 + 64;
    for(int k0=0;k0<kmax;k0+=16){
        int j = m0 + am;
        float4 av;
        if(k0 + 15 <= m0){
            av = *(const float4*)&A[(size_t)j*Sdim + k0+ak];
        } else {
            const float* ap = &A[(size_t)j*Sdim + k0+ak];
            int i0 = k0+ak;
            av.x = (i0+0<=j)?ap[0]:0.f;
            av.y = (i0+1<=j)?ap[1]:0.f;
            av.z = (i0+2<=j)?ap[2]:0.f;
            av.w = (i0+3<=j)?ap[3]:0.f;
        }
        float4 bv = *(const float4*)&Bv[(size_t)(k0+bk)*DHdim + bn];
        As[ak+0][am]=av.x; As[ak+1][am]=av.y; As[ak+2][am]=av.z; As[ak+3][am]=av.w;
        *(float4*)&Bs[bk][bn] = bv;
        __syncthreads();
        GEMM_FMA16();
        __syncthreads();
    }
    float* C = g_attnT + (size_t)bh*Sdim*DHdim;
    #pragma unroll
    for(int i=0;i<4;i++){
        int row = m0 + ty*4 + i;
        float r = g_rinv[(size_t)bh*Sdim + row];
        *(float4*)&C[(size_t)row*DHdim + tx*4] =
            make_float4(acc[i][0]*r, acc[i][1]*r, acc[i][2]*r, acc[i][3]*r);
    }
}

// ============ Kernel 7: out = Wo @ cat + bo  (cat gathered from attnT) =======
// grid (S/64, D/64, B).
__global__ void gemm_wo(const float* __restrict__ Wo, const float* __restrict__ bo,
                        float* __restrict__ out)
{
    __shared__ float As[16][68];
    __shared__ float Bs[16][68];
    int b = blockIdx.z;
    int m0 = blockIdx.y*64, n0 = blockIdx.x*64;
    int tid = threadIdx.x;
    int tx = tid & 15, ty = tid >> 4;
    int am = tid >> 2, ak = (tid & 3)*4;
    int bnB = tid >> 2;          // n offset 0..63
    int bkc = (tid & 3)*4;       // k offset within tile
    float acc[4][4] = {};
    for(int k0=0;k0<512;k0+=16){
        float4 av = *(const float4*)&Wo[(size_t)(m0+am)*512 + k0+ak];
        int h = k0 >> 6, c0 = k0 & 63;
        float4 bv = *(const float4*)&g_attnT[ (((size_t)b*Hdim + h)*Sdim + (n0+bnB))*DHdim + c0 + bkc ];
        As[ak+0][am]=av.x; As[ak+1][am]=av.y; As[ak+2][am]=av.z; As[ak+3][am]=av.w;
        Bs[bkc+0][bnB]=bv.x; Bs[bkc+1][bnB]=bv.y; Bs[bkc+2][bnB]=bv.z; Bs[bkc+3][bnB]=bv.w;
        __syncthreads();
        GEMM_FMA16();
        __syncthreads();
    }
    #pragma unroll
    for(int i=0;i<4;i++){
        int row = m0 + ty*4 + i;
        float e = bo[row];
        *(float4*)&out[((size_t)b*Ddim + row)*Sdim + n0+tx*4] =
            make_float4(acc[i][0]+e, acc[i][1]+e, acc[i][2]+e, acc[i][3]+e);
    }
}

// ============ Kernel 8: res = out + conv ; LN2 over D ; write d_out ==========
// grid (S/16, B), block 512.
__global__ void k_ln2(float* __restrict__ out, const float* __restrict__ g2,
                      const float* __restrict__ b2)
{
    __shared__ float sm[16][513];
    int b = blockIdx.y, s0 = blockIdx.x*16;
    int tid = threadIdx.x;
    const float* convp = g_conv + (size_t)b*Ddim*Sdim;
    float* op = out + (size_t)b*Ddim*Sdim;
    #pragma unroll
    for(int it=0; it<16; ++it){
        int idx = it*512 + tid; int sl = idx & 15, dd = idx >> 4;
        size_t a = (size_t)dd*Sdim + s0 + sl;
        sm[sl][dd] = op[a] + convp[a];
    }
    __syncthreads();
    int wrp = tid>>5, lane = tid&31;
    {
        float sum=0.f, sq=0.f;
        #pragma unroll
        for(int k=0;k<16;k++){ float x = sm[wrp][lane + k*32]; sum+=x; sq+=x*x; }
        sum = warp_sum(sum); sq = warp_sum(sq);
        float mean = sum*(1.0f/512.0f);
        float var  = (sq - 512.0f*mean*mean)*(1.0f/511.0f);
        float inv  = rsqrtf(var + 1e-5f);
        float gg = g2[s0+wrp], bb = b2[s0+wrp];
        #pragma unroll
        for(int k=0;k<16;k++){
            int dd = lane + k*32;
            sm[wrp][dd] = (sm[wrp][dd]-mean)*inv*gg + bb;
        }
    }
    __syncthreads();
    #pragma unroll
    for(int it=0; it<16; ++it){
        int idx = it*512 + tid; int sl = idx & 15, dd = idx >> 4;
        op[(size_t)dd*Sdim + s0 + sl] = sm[sl][dd];
    }
}

// ============================================================================
extern "C" void kernel_launch(void* const* d_in, const int* in_sizes, int n_in,
                              void* d_out, int out_size)
{
    const float* ts     = (const float*)d_in[0];
    const int*   te     = (const int*)  d_in[1];
    const float* conv_w = (const float*)d_in[2];
    const float* conv_b = (const float*)d_in[3];
    const float* pe     = (const float*)d_in[4];
    const float* tsemb  = (const float*)d_in[5];
    const float* g1     = (const float*)d_in[6];
    const float* b1     = (const float*)d_in[7];
    const float* Mw     = (const float*)d_in[8];
    const float* Wq     = (const float*)d_in[9];
    const float* Wk     = (const float*)d_in[10];
    const float* Wv     = (const float*)d_in[11];
    const float* Wo     = (const float*)d_in[12];
    const float* bo     = (const float*)d_in[13];
    const float* g2     = (const float*)d_in[14];
    const float* b2     = (const float*)d_in[15];
    float* out = (float*)d_out;

    k_front   <<<dim3(Sdim/16, Bdim), 512>>>(ts, conv_w, conv_b, pe, g1, b1);
    gemm_dense<<<dim3(Sdim/64, Ddim/64, Bdim), 256>>>(Mw, tsemb, te);
    gemm_qkv  <<<dim3(Sdim/64, 3*Ddim/64, Bdim), 256>>>(Wq, Wk, Wv);
    gemm_sc   <<<dim3(Sdim/64, Sdim/64, Bdim*Hdim), 256>>>();
    k_softmax <<<dim3(Sdim, Bdim*Hdim), 256>>>();
    gemm_av   <<<dim3(1, Sdim/64, Bdim*Hdim), 256>>>();
    gemm_wo   <<<dim3(Sdim/64, Ddim/64, Bdim), 256>>>(Wo, bo, out);
    k_ln2     <<<dim3(Sdim/16, Bdim), 512>>>(out, g2, b2);
}

// round 2
// speedup vs baseline: 1.4397x; 1.4397x over previous
#include <cuda_runtime.h>
#include <math.h>

#define Bdim 16
#define Sdim 1024
#define Ddim 512
#define Hdim 8
#define DHdim 64

// ---------------- scratch ----------------
__device__ float g_conv [Bdim*Ddim*Sdim];
__device__ float g_n1   [Bdim*Ddim*Sdim];
__device__ float g_dense[Bdim*Ddim*Sdim];
__device__ float g_q    [Bdim*Ddim*Sdim];
__device__ float g_k    [Bdim*Ddim*Sdim];
__device__ float g_v    [Bdim*Ddim*Sdim];
__device__ float g_cat  [Bdim*Ddim*Sdim];
__device__ float g_sc   [(size_t)Bdim*Hdim*Sdim*Sdim]; // scT[bh][j][i]
__device__ float g_rinv [Bdim*Hdim*Sdim];

// ---------------- helpers ----------------
__device__ __forceinline__ float warp_sum(float v){
    #pragma unroll
    for(int o=16;o;o>>=1) v += __shfl_xor_sync(0xffffffffu, v, o);
    return v;
}
__device__ __forceinline__ float warp_max(float v){
    #pragma unroll
    for(int o=16;o;o>>=1) v = fmaxf(v, __shfl_xor_sync(0xffffffffu, v, o));
    return v;
}
__device__ __forceinline__ float f2tf(float x){
    unsigned r; asm("cvt.rna.tf32.f32 %0, %1;" : "=r"(r) : "f"(x));
    return __uint_as_float(r);
}
__device__ __forceinline__ void mma8(float* d, const unsigned* a, const unsigned* b){
    asm volatile(
      "mma.sync.aligned.m16n8k8.row.col.f32.tf32.tf32.f32 "
      "{%0,%1,%2,%3}, {%4,%5,%6,%7}, {%8,%9}, {%0,%1,%2,%3};\n"
      : "+f"(d[0]), "+f"(d[1]), "+f"(d[2]), "+f"(d[3])
      : "r"(a[0]), "r"(a[1]), "r"(a[2]), "r"(a[3]), "r"(b[0]), "r"(b[1]));
}

#define GEMM_FMA16()                                                          \
    _Pragma("unroll")                                                         \
    for(int kk=0;kk<16;kk++){                                                 \
        float4 a = *(const float4*)&As[kk][ty*4];                             \
        float4 v = *(const float4*)&Bs[kk][tx*4];                             \
        acc[0][0]+=a.x*v.x; acc[0][1]+=a.x*v.y; acc[0][2]+=a.x*v.z; acc[0][3]+=a.x*v.w; \
        acc[1][0]+=a.y*v.x; acc[1][1]+=a.y*v.y; acc[1][2]+=a.y*v.z; acc[1][3]+=a.y*v.w; \
        acc[2][0]+=a.z*v.x; acc[2][1]+=a.z*v.y; acc[2][2]+=a.z*v.z; acc[2][3]+=a.z*v.w; \
        acc[3][0]+=a.w*v.x; acc[3][1]+=a.w*v.y; acc[3][2]+=a.w*v.z; acc[3][3]+=a.w*v.w; \
    }

// ============ Kernel 1: conv + pe + gelu + LN1 ==============================
__global__ void k_front(const float* __restrict__ ts, const float* __restrict__ cw,
                        const float* __restrict__ cb, const float* __restrict__ pe,
                        const float* __restrict__ g1, const float* __restrict__ b1)
{
    __shared__ float sm[16][513];
    int b = blockIdx.y, s0 = blockIdx.x*16;
    int tid = threadIdx.x;
    int d = tid;
    float w0=cw[d*4+0], w1=cw[d*4+1], w2=cw[d*4+2], w3=cw[d*4+3];
    float bias = cb[d];
    const float* tsb = ts + b*4096;
    #pragma unroll
    for(int sl=0; sl<16; ++sl){
        int s = s0+sl;
        sm[sl][d] = bias + pe[s*Ddim + d]
                  + tsb[s*4+0]*w0 + tsb[s*4+1]*w1 + tsb[s*4+2]*w2 + tsb[s*4+3]*w3;
    }
    __syncthreads();
    float* convp = g_conv + (size_t)b*Ddim*Sdim;
    #pragma unroll
    for(int it=0; it<16; ++it){
        int idx = it*512 + tid; int sl = idx & 15, dd = idx >> 4;
        convp[(size_t)dd*Sdim + s0 + sl] = sm[sl][dd];
    }
    __syncthreads();
    #pragma unroll
    for(int sl=0; sl<16; ++sl){
        float x = sm[sl][d];
        sm[sl][d] = 0.5f*x*(1.0f + erff(x*0.70710678118654752f));
    }
    __syncthreads();
    int wrp = tid>>5, lane = tid&31;
    {
        float sum=0.f, sq=0.f;
        #pragma unroll
        for(int k=0;k<16;k++){ float x = sm[wrp][lane + k*32]; sum+=x; sq+=x*x; }
        sum = warp_sum(sum); sq = warp_sum(sq);
        float mean = sum*(1.0f/512.0f);
        float var  = (sq - 512.0f*mean*mean)*(1.0f/511.0f);
        float inv  = rsqrtf(var + 1e-5f);
        float gg = g1[s0+wrp], bb = b1[s0+wrp];
        #pragma unroll
        for(int k=0;k<16;k++){
            int dd = lane + k*32;
            sm[wrp][dd] = (sm[wrp][dd]-mean)*inv*gg + bb;
        }
    }
    __syncthreads();
    float* n1p = g_n1 + (size_t)b*Ddim*Sdim;
    #pragma unroll
    for(int it=0; it<16; ++it){
        int idx = it*512 + tid; int sl = idx & 15, dd = idx >> 4;
        n1p[(size_t)dd*Sdim + s0 + sl] = sm[sl][dd];
    }
}

// ============ tf32 MMA GEMM: C[b] = W(512x512) @ X[b](512x1024) =============
// modes: 0 dense (B=g_n1, C=g_dense, +emb)   1/2/3 q/k/v (B=g_dense)
//        4 wo (B=g_cat, C=Cout, +bias)
// tile 128(m) x 64(n), BK=16, 256 threads (8 warps: 2m x 4n).
__global__ __launch_bounds__(256) void gemm_tf32(
    const float* __restrict__ W, float* __restrict__ Cout,
    const float* __restrict__ bias, const float* __restrict__ tsemb,
    const int* __restrict__ te, int mode)
{
    __shared__ float As[2][16][132];
    __shared__ float Bs[2][16][68];
    int b = blockIdx.z;
    int n0 = blockIdx.x*64, m0 = blockIdx.y*128;
    const float* Bsel = (mode==0) ? g_n1 : (mode==4 ? g_cat : g_dense);
    float* Csel;
    if(mode==0) Csel = g_dense;
    else if(mode==1) Csel = g_q;
    else if(mode==2) Csel = g_k;
    else if(mode==3) Csel = g_v;
    else Csel = Cout;
    const float* Bm = Bsel + (size_t)b*Ddim*Sdim;
    float* C = Csel + (size_t)b*Ddim*Sdim;

    int tid = threadIdx.x, lane = tid&31, wid = tid>>5;
    int wm = wid&1, wn = wid>>1;
    int am = tid>>2, akq = (tid&3)*4;      // A rows am/am+64, k cols akq..+3
    int bk = tid>>4, bnq = (tid&15)*4;     // B row bk, cols bnq..+3

    float4 pa0 = *(const float4*)&W[(size_t)(m0+am)*512 + akq];
    float4 pa1 = *(const float4*)&W[(size_t)(m0+am+64)*512 + akq];
    float4 pb0 = *(const float4*)&Bm[(size_t)bk*Sdim + n0+bnq];

    float acc[4][2][4];
    #pragma unroll
    for(int i=0;i<4;i++)
      #pragma unroll
      for(int j=0;j<2;j++)
        #pragma unroll
        for(int k=0;k<4;k++) acc[i][j][k]=0.f;

    int st = 0;
    for(int k0=0;;){
        As[st][akq+0][am]    = f2tf(pa0.x);
        As[st][akq+1][am]    = f2tf(pa0.y);
        As[st][akq+2][am]    = f2tf(pa0.z);
        As[st][akq+3][am]    = f2tf(pa0.w);
        As[st][akq+0][am+64] = f2tf(pa1.x);
        As[st][akq+1][am+64] = f2tf(pa1.y);
        As[st][akq+2][am+64] = f2tf(pa1.z);
        As[st][akq+3][am+64] = f2tf(pa1.w);
        Bs[st][bk][bnq+0] = f2tf(pb0.x);
        Bs[st][bk][bnq+1] = f2tf(pb0.y);
        Bs[st][bk][bnq+2] = f2tf(pb0.z);
        Bs[st][bk][bnq+3] = f2tf(pb0.w);
        __syncthreads();
        k0 += 16;
        bool more = (k0 < 512);
        if(more){
            pa0 = *(const float4*)&W[(size_t)(m0+am)*512 + k0+akq];
            pa1 = *(const float4*)&W[(size_t)(m0+am+64)*512 + k0+akq];
            pb0 = *(const float4*)&Bm[(size_t)(k0+bk)*Sdim + n0+bnq];
        }
        #pragma unroll
        for(int kk=0;kk<16;kk+=8){
            unsigned af[4][4], bf[2][2];
            int kA = kk + (lane&3);
            int rA = lane>>2;
            #pragma unroll
            for(int mt=0;mt<4;mt++){
                int m = wm*64 + mt*16 + rA;
                af[mt][0] = __float_as_uint(As[st][kA][m]);
                af[mt][1] = __float_as_uint(As[st][kA][m+8]);
                af[mt][2] = __float_as_uint(As[st][kA+4][m]);
                af[mt][3] = __float_as_uint(As[st][kA+4][m+8]);
            }
            #pragma unroll
            for(int nt=0;nt<2;nt++){
                int n = wn*16 + nt*8 + rA;
                bf[nt][0] = __float_as_uint(Bs[st][kA][n]);
                bf[nt][1] = __float_as_uint(Bs[st][kA+4][n]);
            }
            #pragma unroll
            for(int mt=0;mt<4;mt++)
                #pragma unroll
                for(int nt=0;nt<2;nt++)
                    mma8(acc[mt][nt], af[mt], bf[nt]);
        }
        st ^= 1;
        if(!more) break;
    }

    const float* embp = (mode==0) ? (tsemb + (size_t)te[b]*512) : 0;
    #pragma unroll
    for(int mt=0;mt<4;mt++){
        #pragma unroll
        for(int h2=0;h2<2;h2++){
            int r = m0 + wm*64 + mt*16 + (lane>>2) + h2*8;
            float addv = 0.f;
            if(mode==0) addv = embp[r];
            else if(mode==4) addv = bias[r];
            #pragma unroll
            for(int nt=0;nt<2;nt++){
                int col = n0 + wn*16 + nt*8 + 2*(lane&3);
                float2 v;
                v.x = acc[mt][nt][h2*2+0] + addv;
                v.y = acc[mt][nt][h2*2+1] + addv;
                *(float2*)&C[(size_t)r*Sdim + col] = v;
            }
        }
    }
}

// ============ tf32 MMA scores: scT[j,i] = (K_j . Q_i)/8, causal tiles ========
// tile 128(j=m) x 64(i=n), K=64 over c. A=K (k-major in mem), B=Q.
__global__ __launch_bounds__(256) void gemm_sc_mma()
{
    __shared__ float As[2][16][132];
    __shared__ float Bs[2][16][68];
    int bh = blockIdx.z;
    int m0 = blockIdx.y*128;   // j
    int n0 = blockIdx.x*64;    // i
    if(n0 >= m0+128) return;
    const float* Kp = g_k + (size_t)bh*DHdim*Sdim;
    const float* Qp = g_q + (size_t)bh*DHdim*Sdim;

    int tid = threadIdx.x, lane = tid&31, wid = tid>>5;
    int wm = wid&1, wn = wid>>1;
    int ac = tid>>4, ajq = (tid&15)*4;   // A: c row, j cols (two halves)
    int bc = tid>>4, biq = (tid&15)*4;   // B: c row, i cols

    float4 pa0 = *(const float4*)&Kp[(size_t)ac*Sdim + m0+ajq];
    float4 pa1 = *(const float4*)&Kp[(size_t)ac*Sdim + m0+ajq+64];
    float4 pb0 = *(const float4*)&Qp[(size_t)bc*Sdim + n0+biq];

    float acc[4][2][4];
    #pragma unroll
    for(int i=0;i<4;i++)
      #pragma unroll
      for(int j=0;j<2;j++)
        #pragma unroll
        for(int k=0;k<4;k++) acc[i][j][k]=0.f;

    int st = 0;
    for(int k0=0;;){
        *(float4*)&As[st][ac][ajq]    = make_float4(f2tf(pa0.x),f2tf(pa0.y),f2tf(pa0.z),f2tf(pa0.w));
        *(float4*)&As[st][ac][ajq+64] = make_float4(f2tf(pa1.x),f2tf(pa1.y),f2tf(pa1.z),f2tf(pa1.w));
        *(float4*)&Bs[st][bc][biq]    = make_float4(f2tf(pb0.x),f2tf(pb0.y),f2tf(pb0.z),f2tf(pb0.w));
        __syncthreads();
        k0 += 16;
        bool more = (k0 < 64);
        if(more){
            pa0 = *(const float4*)&Kp[(size_t)(k0+ac)*Sdim + m0+ajq];
            pa1 = *(const float4*)&Kp[(size_t)(k0+ac)*Sdim + m0+ajq+64];
            pb0 = *(const float4*)&Qp[(size_t)(k0+bc)*Sdim + n0+biq];
        }
        #pragma unroll
        for(int kk=0;kk<16;kk+=8){
            unsigned af[4][4], bf[2][2];
            int kA = kk + (lane&3);
            int rA = lane>>2;
            #pragma unroll
            for(int mt=0;mt<4;mt++){
                int m = wm*64 + mt*16 + rA;
                af[mt][0] = __float_as_uint(As[st][kA][m]);
                af[mt][1] = __float_as_uint(As[st][kA][m+8]);
                af[mt][2] = __float_as_uint(As[st][kA+4][m]);
                af[mt][3] = __float_as_uint(As[st][kA+4][m+8]);
            }
            #pragma unroll
            for(int nt=0;nt<2;nt++){
                int n = wn*16 + nt*8 + rA;
                bf[nt][0] = __float_as_uint(Bs[st][kA][n]);
                bf[nt][1] = __float_as_uint(Bs[st][kA+4][n]);
            }
            #pragma unroll
            for(int mt=0;mt<4;mt++)
                #pragma unroll
                for(int nt=0;nt<2;nt++)
                    mma8(acc[mt][nt], af[mt], bf[nt]);
        }
        st ^= 1;
        if(!more) break;
    }

    float* Cp = g_sc + (size_t)bh*Sdim*Sdim;
    #pragma unroll
    for(int mt=0;mt<4;mt++){
        #pragma unroll
        for(int h2=0;h2<2;h2++){
            int r = m0 + wm*64 + mt*16 + (lane>>2) + h2*8;
            #pragma unroll
            for(int nt=0;nt<2;nt++){
                int col = n0 + wn*16 + nt*8 + 2*(lane&3);
                float2 v;
                v.x = acc[mt][nt][h2*2+0]*0.125f;
                v.y = acc[mt][nt][h2*2+1]*0.125f;
                *(float2*)&Cp[(size_t)r*Sdim + col] = v;
            }
        }
    }
}

// ============ softmax over i<=j (exp only), 1/sum to g_rinv =================
__global__ void k_softmax()
{
    int j = blockIdx.x, bh = blockIdx.y;
    float* row = g_sc + ((size_t)bh*Sdim + j)*Sdim;
    int n = j+1;
    int tid = threadIdx.x, lane = tid&31, wrp = tid>>5;
    __shared__ float red[8];
    float m = -1e30f;
    for(int i=tid;i<n;i+=256) m = fmaxf(m, row[i]);
    m = warp_max(m);
    if(lane==0) red[wrp]=m;
    __syncthreads();
    if(wrp==0){
        float t = (lane<8) ? red[lane] : -1e30f;
        t = warp_max(t);
        if(lane==0) red[0]=t;
    }
    __syncthreads();
    float M = red[0];
    __syncthreads();
    float s = 0.f;
    for(int i=tid;i<n;i+=256){
        float e = __expf(row[i]-M);
        row[i] = e;
        s += e;
    }
    s = warp_sum(s);
    if(lane==0) red[wrp]=s;
    __syncthreads();
    if(wrp==0){
        float t = (lane<8) ? red[lane] : 0.f;
        t = warp_sum(t);
        if(lane==0) g_rinv[(size_t)bh*Sdim + j] = 1.0f/t;
    }
}

// ============ AV: cat[c][j] = rinv[j] * sum_{i<=j} V[c][i] p[j][i] ==========
// tile 64(c) x 64(j), SIMT. grid (S/64, B*H).
__global__ __launch_bounds__(256) void gemm_av()
{
    __shared__ float As[16][68];
    __shared__ float Bs[16][68];
    int bh = blockIdx.y; int b = bh>>3, h = bh&7;
    int j0 = blockIdx.x*64;
    const float* V = g_v + ((size_t)b*Ddim + h*64)*Sdim;
    const float* P = g_sc + (size_t)bh*Sdim*Sdim;
    int tid = threadIdx.x;
    int tx = tid&15, ty = tid>>4;
    int ac = tid>>2, akq = (tid&3)*4;
    int bj = tid>>2, biq = (tid&3)*4;
    float acc[4][4] = {};
    int kmax = j0+64;
    for(int k0=0;k0<kmax;k0+=16){
        float4 av4 = *(const float4*)&V[(size_t)ac*Sdim + k0+akq];
        int jg = j0 + bj;
        const float* pp = &P[(size_t)jg*Sdim + k0+biq];
        float4 bv;
        if(k0+15 <= j0){
            bv = *(const float4*)pp;
        } else {
            int i0 = k0+biq;
            bv.x = (i0+0<=jg)?pp[0]:0.f;
            bv.y = (i0+1<=jg)?pp[1]:0.f;
            bv.z = (i0+2<=jg)?pp[2]:0.f;
            bv.w = (i0+3<=jg)?pp[3]:0.f;
        }
        As[akq+0][ac]=av4.x; As[akq+1][ac]=av4.y; As[akq+2][ac]=av4.z; As[akq+3][ac]=av4.w;
        Bs[biq+0][bj]=bv.x;  Bs[biq+1][bj]=bv.y;  Bs[biq+2][bj]=bv.z;  Bs[biq+3][bj]=bv.w;
        __syncthreads();
        GEMM_FMA16();
        __syncthreads();
    }
    const float* rv = g_rinv + (size_t)bh*Sdim + j0;
    float r0=rv[tx*4+0], r1=rv[tx*4+1], r2=rv[tx*4+2], r3=rv[tx*4+3];
    float* C = g_cat + ((size_t)b*Ddim + h*64)*Sdim;
    #pragma unroll
    for(int i=0;i<4;i++){
        int c = ty*4+i;
        *(float4*)&C[(size_t)c*Sdim + j0 + tx*4] =
            make_float4(acc[i][0]*r0, acc[i][1]*r1, acc[i][2]*r2, acc[i][3]*r3);
    }
}

// ============ residual + LN2 ================================================
__global__ void k_ln2(float* __restrict__ out, const float* __restrict__ g2,
                      const float* __restrict__ b2)
{
    __shared__ float sm[16][513];
    int b = blockIdx.y, s0 = blockIdx.x*16;
    int tid = threadIdx.x;
    const float* convp = g_conv + (size_t)b*Ddim*Sdim;
    float* op = out + (size_t)b*Ddim*Sdim;
    #pragma unroll
    for(int it=0; it<16; ++it){
        int idx = it*512 + tid; int sl = idx & 15, dd = idx >> 4;
        size_t a = (size_t)dd*Sdim + s0 + sl;
        sm[sl][dd] = op[a] + convp[a];
    }
    __syncthreads();
    int wrp = tid>>5, lane = tid&31;
    {
        float sum=0.f, sq=0.f;
        #pragma unroll
        for(int k=0;k<16;k++){ float x = sm[wrp][lane + k*32]; sum+=x; sq+=x*x; }
        sum = warp_sum(sum); sq = warp_sum(sq);
        float mean = sum*(1.0f/512.0f);
        float var  = (sq - 512.0f*mean*mean)*(1.0f/511.0f);
        float inv  = rsqrtf(var + 1e-5f);
        float gg = g2[s0+wrp], bb = b2[s0+wrp];
        #pragma unroll
        for(int k=0;k<16;k++){
            int dd = lane + k*32;
            sm[wrp][dd] = (sm[wrp][dd]-mean)*inv*gg + bb;
        }
    }
    __syncthreads();
    #pragma unroll
    for(int it=0; it<16; ++it){
        int idx = it*512 + tid; int sl = idx & 15, dd = idx >> 4;
        op[(size_t)dd*Sdim + s0 + sl] = sm[sl][dd];
    }
}

// ============================================================================
extern "C" void kernel_launch(void* const* d_in, const int* in_sizes, int n_in,
                              void* d_out, int out_size)
{
    const float* ts     = (const float*)d_in[0];
    const int*   te     = (const int*)  d_in[1];
    const float* conv_w = (const float*)d_in[2];
    const float* conv_b = (const float*)d_in[3];
    const float* pe     = (const float*)d_in[4];
    const float* tsemb  = (const float*)d_in[5];
    const float* g1     = (const float*)d_in[6];
    const float* b1     = (const float*)d_in[7];
    const float* Mw     = (const float*)d_in[8];
    const float* Wq     = (const float*)d_in[9];
    const float* Wk     = (const float*)d_in[10];
    const float* Wv     = (const float*)d_in[11];
    const float* Wo     = (const float*)d_in[12];
    const float* bo     = (const float*)d_in[13];
    const float* g2     = (const float*)d_in[14];
    const float* b2     = (const float*)d_in[15];
    float* out = (float*)d_out;

    dim3 gg(Sdim/64, Ddim/128, Bdim);   // (16,4,16)
    k_front    <<<dim3(Sdim/16, Bdim), 512>>>(ts, conv_w, conv_b, pe, g1, b1);
    gemm_tf32  <<<gg, 256>>>(Mw, 0, 0, tsemb, te, 0);
    gemm_tf32  <<<gg, 256>>>(Wq, 0, 0, 0, 0, 1);
    gemm_tf32  <<<gg, 256>>>(Wk, 0, 0, 0, 0, 2);
    gemm_tf32  <<<gg, 256>>>(Wv, 0, 0, 0, 0, 3);
    gemm_sc_mma<<<dim3(Sdim/64, Sdim/128, Bdim*Hdim), 256>>>();
    k_softmax  <<<dim3(Sdim, Bdim*Hdim), 256>>>();
    gemm_av    <<<dim3(Sdim/64, Bdim*Hdim), 256>>>();
    gemm_tf32  <<<gg, 256>>>(Wo, out, bo, 0, 0, 4);
    k_ln2      <<<dim3(Sdim/16, Bdim), 512>>>(out, g2, b2);
}

// round 3
// speedup vs baseline: 1.9108x; 1.3272x over previous
#include <cuda_runtime.h>
#include <math.h>

#define Bdim 16
#define Sdim 1024
#define Ddim 512
#define Hdim 8
#define DHdim 64

// ---------------- scratch ----------------
__device__ float g_w    [5*Ddim*Ddim];              // rounded weights: M,Wq,Wk,Wv,Wo
__device__ float g_conv [Bdim*Ddim*Sdim];
__device__ float g_n1   [Bdim*Ddim*Sdim];
__device__ float g_dense[Bdim*Ddim*Sdim];
__device__ float g_q    [Bdim*Ddim*Sdim];
__device__ float g_k    [Bdim*Ddim*Sdim];
__device__ float g_vt   [Bdim*Hdim*Sdim*DHdim];     // (b,h,s,c)
__device__ float g_cat  [Bdim*Ddim*Sdim];
__device__ float g_sc   [(size_t)Bdim*Hdim*Sdim*Sdim]; // scT[bh][j][i]
__device__ float g_rinv [Bdim*Hdim*Sdim];

// ---------------- helpers ----------------
__device__ __forceinline__ float warp_sum(float v){
    #pragma unroll
    for(int o=16;o;o>>=1) v += __shfl_xor_sync(0xffffffffu, v, o);
    return v;
}
__device__ __forceinline__ float warp_max(float v){
    #pragma unroll
    for(int o=16;o;o>>=1) v = fmaxf(v, __shfl_xor_sync(0xffffffffu, v, o));
    return v;
}
__device__ __forceinline__ float f2tf(float x){
    unsigned r; asm("cvt.rna.tf32.f32 %0, %1;" : "=r"(r) : "f"(x));
    return __uint_as_float(r);
}
__device__ __forceinline__ void mma8(float* d, const unsigned* a, const unsigned* b){
    asm volatile(
      "mma.sync.aligned.m16n8k8.row.col.f32.tf32.tf32.f32 "
      "{%0,%1,%2,%3}, {%4,%5,%6,%7}, {%8,%9}, {%0,%1,%2,%3};\n"
      : "+f"(d[0]), "+f"(d[1]), "+f"(d[2]), "+f"(d[3])
      : "r"(a[0]), "r"(a[1]), "r"(a[2]), "r"(a[3]), "r"(b[0]), "r"(b[1]));
}

// ============ Kernel 0: round weights to tf32 once ==========================
__global__ void k_prep(const float* __restrict__ Mw, const float* __restrict__ Wq,
                       const float* __restrict__ Wk, const float* __restrict__ Wv,
                       const float* __restrict__ Wo)
{
    int idx = (blockIdx.x*256 + threadIdx.x)*4;          // over 5*262144 floats
    int w = idx >> 18, off = idx & 262143;
    const float* src = (w==0)?Mw:(w==1)?Wq:(w==2)?Wk:(w==3)?Wv:Wo;
    float4 v = *(const float4*)&src[off];
    v.x=f2tf(v.x); v.y=f2tf(v.y); v.z=f2tf(v.z); v.w=f2tf(v.w);
    *(float4*)&g_w[idx] = v;
}

// ============ Kernel 1: conv + pe + gelu + LN1 ==============================
__global__ void k_front(const float* __restrict__ ts, const float* __restrict__ cw,
                        const float* __restrict__ cb, const float* __restrict__ pe,
                        const float* __restrict__ g1, const float* __restrict__ b1)
{
    __shared__ float sm[16][513];
    int b = blockIdx.y, s0 = blockIdx.x*16;
    int tid = threadIdx.x;
    int d = tid;
    float w0=cw[d*4+0], w1=cw[d*4+1], w2=cw[d*4+2], w3=cw[d*4+3];
    float bias = cb[d];
    const float* tsb = ts + b*4096;
    #pragma unroll
    for(int sl=0; sl<16; ++sl){
        int s = s0+sl;
        sm[sl][d] = bias + pe[s*Ddim + d]
                  + tsb[s*4+0]*w0 + tsb[s*4+1]*w1 + tsb[s*4+2]*w2 + tsb[s*4+3]*w3;
    }
    __syncthreads();
    float* convp = g_conv + (size_t)b*Ddim*Sdim;
    #pragma unroll
    for(int it=0; it<16; ++it){
        int idx = it*512 + tid; int sl = idx & 15, dd = idx >> 4;
        convp[(size_t)dd*Sdim + s0 + sl] = sm[sl][dd];
    }
    __syncthreads();
    #pragma unroll
    for(int sl=0; sl<16; ++sl){
        float x = sm[sl][d];
        sm[sl][d] = 0.5f*x*(1.0f + erff(x*0.70710678118654752f));
    }
    __syncthreads();
    int wrp = tid>>5, lane = tid&31;
    {
        float sum=0.f, sq=0.f;
        #pragma unroll
        for(int k=0;k<16;k++){ float x = sm[wrp][lane + k*32]; sum+=x; sq+=x*x; }
        sum = warp_sum(sum); sq = warp_sum(sq);
        float mean = sum*(1.0f/512.0f);
        float var  = (sq - 512.0f*mean*mean)*(1.0f/511.0f);
        float inv  = rsqrtf(var + 1e-5f);
        float gg = g1[s0+wrp], bb = b1[s0+wrp];
        #pragma unroll
        for(int k=0;k<16;k++){
            int dd = lane + k*32;
            sm[wrp][dd] = (sm[wrp][dd]-mean)*inv*gg + bb;
        }
    }
    __syncthreads();
    float* n1p = g_n1 + (size_t)b*Ddim*Sdim;
    #pragma unroll
    for(int it=0; it<16; ++it){
        int idx = it*512 + tid; int sl = idx & 15, dd = idx >> 4;
        n1p[(size_t)dd*Sdim + s0 + sl] = f2tf(sm[sl][dd]);
    }
}

// ============ tf32 MMA GEMM 128x128x16: C[b] = W @ X[b] =====================
// modes: 0 dense(+emb, ->g_dense tf32) 1 q 2 k 3 v->g_vt  4 wo(+bias ->out fp32)
__global__ __launch_bounds__(256) void gemm_tf32(
    float* __restrict__ Cout, const float* __restrict__ bias,
    const float* __restrict__ tsemb, const int* __restrict__ te, int mode)
{
    __shared__ float As[2][16][136];
    __shared__ float Bs[2][16][136];
    int b = blockIdx.z;
    int n0 = blockIdx.x*128, m0 = blockIdx.y*128;
    int wsel = (mode==4) ? 4 : mode;
    const float* W = g_w + (size_t)wsel*262144;
    const float* Bsel = (mode==0) ? g_n1 : (mode==4 ? g_cat : g_dense);
    const float* Bm = Bsel + (size_t)b*Ddim*Sdim;

    int tid = threadIdx.x, lane = tid&31, wid = tid>>5;
    int wm = wid&1, wn = wid>>1;
    int am = tid>>2, akq = (tid&3)*4;
    int bk = tid>>4, bnq = (tid&15)*8;

    float4 pa0 = *(const float4*)&W[(size_t)(m0+am)*512 + akq];
    float4 pa1 = *(const float4*)&W[(size_t)(m0+am+64)*512 + akq];
    float4 pb0 = *(const float4*)&Bm[(size_t)bk*Sdim + n0+bnq];
    float4 pb1 = *(const float4*)&Bm[(size_t)bk*Sdim + n0+bnq+4];

    float acc[4][4][4];
    #pragma unroll
    for(int i=0;i<4;i++)
      #pragma unroll
      for(int j=0;j<4;j++)
        #pragma unroll
        for(int k=0;k<4;k++) acc[i][j][k]=0.f;

    int st = 0;
    for(int k0=0;;){
        As[st][akq+0][am]    = pa0.x;
        As[st][akq+1][am]    = pa0.y;
        As[st][akq+2][am]    = pa0.z;
        As[st][akq+3][am]    = pa0.w;
        As[st][akq+0][am+64] = pa1.x;
        As[st][akq+1][am+64] = pa1.y;
        As[st][akq+2][am+64] = pa1.z;
        As[st][akq+3][am+64] = pa1.w;
        *(float4*)&Bs[st][bk][bnq]   = pb0;
        *(float4*)&Bs[st][bk][bnq+4] = pb1;
        __syncthreads();
        k0 += 16;
        bool more = (k0 < 512);
        if(more){
            pa0 = *(const float4*)&W[(size_t)(m0+am)*512 + k0+akq];
            pa1 = *(const float4*)&W[(size_t)(m0+am+64)*512 + k0+akq];
            pb0 = *(const float4*)&Bm[(size_t)(k0+bk)*Sdim + n0+bnq];
            pb1 = *(const float4*)&Bm[(size_t)(k0+bk)*Sdim + n0+bnq+4];
        }
        #pragma unroll
        for(int kk=0;kk<16;kk+=8){
            unsigned af[4][4], bf[4][2];
            int kA = kk + (lane&3);
            int rA = lane>>2;
            #pragma unroll
            for(int mt=0;mt<4;mt++){
                int m = wm*64 + mt*16 + rA;
                af[mt][0] = __float_as_uint(As[st][kA][m]);
                af[mt][1] = __float_as_uint(As[st][kA][m+8]);
                af[mt][2] = __float_as_uint(As[st][kA+4][m]);
                af[mt][3] = __float_as_uint(As[st][kA+4][m+8]);
            }
            #pragma unroll
            for(int nt=0;nt<4;nt++){
                int n = wn*32 + nt*8 + rA;
                bf[nt][0] = __float_as_uint(Bs[st][kA][n]);
                bf[nt][1] = __float_as_uint(Bs[st][kA+4][n]);
            }
            #pragma unroll
            for(int mt=0;mt<4;mt++)
                #pragma unroll
                for(int nt=0;nt<4;nt++)
                    mma8(acc[mt][nt], af[mt], bf[nt]);
        }
        st ^= 1;
        if(!more) break;
    }

    float* Csel;
    if(mode==0) Csel = g_dense;
    else if(mode==1) Csel = g_q;
    else if(mode==2) Csel = g_k;
    else Csel = Cout;                     // mode 4 (mode 3 handled below)
    const float* embp = (mode==0) ? (tsemb + (size_t)te[b]*512) : 0;

    if(mode==3){
        // scatter V into g_vt[b][h][s][c]
        #pragma unroll
        for(int mt=0;mt<4;mt++){
            #pragma unroll
            for(int h2=0;h2<2;h2++){
                int r = m0 + wm*64 + mt*16 + (lane>>2) + h2*8;  // d = h*64+c
                int h = r>>6, c = r&63;
                float* vtp = g_vt + (((size_t)b*Hdim + h)*Sdim)*DHdim + c;
                #pragma unroll
                for(int nt=0;nt<4;nt++){
                    int col = n0 + wn*32 + nt*8 + 2*(lane&3);   // s
                    vtp[(size_t)col*DHdim]     = f2tf(acc[mt][nt][h2*2+0]);
                    vtp[(size_t)(col+1)*DHdim] = f2tf(acc[mt][nt][h2*2+1]);
                }
            }
        }
        return;
    }

    float* C = Csel + (size_t)b*Ddim*Sdim;
    #pragma unroll
    for(int mt=0;mt<4;mt++){
        #pragma unroll
        for(int h2=0;h2<2;h2++){
            int r = m0 + wm*64 + mt*16 + (lane>>2) + h2*8;
            float addv = 0.f;
            if(mode==0) addv = embp[r];
            else if(mode==4) addv = bias[r];
            #pragma unroll
            for(int nt=0;nt<4;nt++){
                int col = n0 + wn*32 + nt*8 + 2*(lane&3);
                float2 v;
                if(mode==4){
                    v.x = acc[mt][nt][h2*2+0] + addv;
                    v.y = acc[mt][nt][h2*2+1] + addv;
                } else {
                    v.x = f2tf(acc[mt][nt][h2*2+0] + addv);
                    v.y = f2tf(acc[mt][nt][h2*2+1] + addv);
                }
                *(float2*)&C[(size_t)r*Sdim + col] = v;
            }
        }
    }
}

// ============ tf32 MMA scores: scT[j,i] = (K_j . Q_i)/8, causal tiles ========
__global__ __launch_bounds__(256) void gemm_sc_mma()
{
    __shared__ float As[2][16][136];
    __shared__ float Bs[2][16][72];
    int bh = blockIdx.z;
    int m0 = blockIdx.y*128;   // j
    int n0 = blockIdx.x*64;    // i
    if(n0 >= m0+128) return;
    const float* Kp = g_k + (size_t)bh*DHdim*Sdim;
    const float* Qp = g_q + (size_t)bh*DHdim*Sdim;

    int tid = threadIdx.x, lane = tid&31, wid = tid>>5;
    int wm = wid&1, wn = wid>>1;
    int ac = tid>>4, ajq = (tid&15)*4;
    int bc = tid>>4, biq = (tid&15)*4;

    float4 pa0 = *(const float4*)&Kp[(size_t)ac*Sdim + m0+ajq];
    float4 pa1 = *(const float4*)&Kp[(size_t)ac*Sdim + m0+ajq+64];
    float4 pb0 = *(const float4*)&Qp[(size_t)bc*Sdim + n0+biq];

    float acc[4][2][4];
    #pragma unroll
    for(int i=0;i<4;i++)
      #pragma unroll
      for(int j=0;j<2;j++)
        #pragma unroll
        for(int k=0;k<4;k++) acc[i][j][k]=0.f;

    int st = 0;
    for(int k0=0;;){
        *(float4*)&As[st][ac][ajq]    = pa0;
        *(float4*)&As[st][ac][ajq+64] = pa1;
        *(float4*)&Bs[st][bc][biq]    = pb0;
        __syncthreads();
        k0 += 16;
        bool more = (k0 < 64);
        if(more){
            pa0 = *(const float4*)&Kp[(size_t)(k0+ac)*Sdim + m0+ajq];
            pa1 = *(const float4*)&Kp[(size_t)(k0+ac)*Sdim + m0+ajq+64];
            pb0 = *(const float4*)&Qp[(size_t)(k0+bc)*Sdim + n0+biq];
        }
        #pragma unroll
        for(int kk=0;kk<16;kk+=8){
            unsigned af[4][4], bf[2][2];
            int kA = kk + (lane&3);
            int rA = lane>>2;
            #pragma unroll
            for(int mt=0;mt<4;mt++){
                int m = wm*64 + mt*16 + rA;
                af[mt][0] = __float_as_uint(As[st][kA][m]);
                af[mt][1] = __float_as_uint(As[st][kA][m+8]);
                af[mt][2] = __float_as_uint(As[st][kA+4][m]);
                af[mt][3] = __float_as_uint(As[st][kA+4][m+8]);
            }
            #pragma unroll
            for(int nt=0;nt<2;nt++){
                int n = wn*16 + nt*8 + rA;
                bf[nt][0] = __float_as_uint(Bs[st][kA][n]);
                bf[nt][1] = __float_as_uint(Bs[st][kA+4][n]);
            }
            #pragma unroll
            for(int mt=0;mt<4;mt++)
                #pragma unroll
                for(int nt=0;nt<2;nt++)
                    mma8(acc[mt][nt], af[mt], bf[nt]);
        }
        st ^= 1;
        if(!more) break;
    }

    float* Cp = g_sc + (size_t)bh*Sdim*Sdim;
    #pragma unroll
    for(int mt=0;mt<4;mt++){
        #pragma unroll
        for(int h2=0;h2<2;h2++){
            int r = m0 + wm*64 + mt*16 + (lane>>2) + h2*8;
            #pragma unroll
            for(int nt=0;nt<2;nt++){
                int col = n0 + wn*16 + nt*8 + 2*(lane&3);
                float2 v;
                v.x = acc[mt][nt][h2*2+0]*0.125f;
                v.y = acc[mt][nt][h2*2+1]*0.125f;
                *(float2*)&Cp[(size_t)r*Sdim + col] = v;
            }
        }
    }
}

// ============ softmax over i<=j (exp only, tf32-rounded), 1/sum to g_rinv ====
__global__ void k_softmax()
{
    int j = blockIdx.x, bh = blockIdx.y;
    float* row = g_sc + ((size_t)bh*Sdim + j)*Sdim;
    int n = j+1;
    int tid = threadIdx.x, lane = tid&31, wrp = tid>>5;
    __shared__ float red[8];
    float m = -1e30f;
    for(int i=tid;i<n;i+=256) m = fmaxf(m, row[i]);
    m = warp_max(m);
    if(lane==0) red[wrp]=m;
    __syncthreads();
    if(wrp==0){
        float t = (lane<8) ? red[lane] : -1e30f;
        t = warp_max(t);
        if(lane==0) red[0]=t;
    }
    __syncthreads();
    float M = red[0];
    __syncthreads();
    float s = 0.f;
    for(int i=tid;i<n;i+=256){
        float e = __expf(row[i]-M);
        row[i] = f2tf(e);
        s += e;
    }
    s = warp_sum(s);
    if(lane==0) red[wrp]=s;
    __syncthreads();
    if(wrp==0){
        float t = (lane<8) ? red[lane] : 0.f;
        t = warp_sum(t);
        if(lane==0) g_rinv[(size_t)bh*Sdim + j] = 1.0f/t;
    }
}

// ============ AV tf32 MMA: attnT[j,c] -> g_cat[c][j] with rinv ==============
// tile 128(j=m) x 64(c=n), K=i up to tile diag. A=P row-major, B=Vt.
__global__ __launch_bounds__(256) void gemm_av_mma()
{
    __shared__ float As[2][16][136];
    __shared__ float Bs[2][16][72];
    int bh = blockIdx.y; int b = bh>>3, h = bh&7;
    int m0 = blockIdx.x*128;
    const float* P  = g_sc + (size_t)bh*Sdim*Sdim;
    const float* Vt = g_vt + ((size_t)bh*Sdim)*DHdim;

    int tid = threadIdx.x, lane = tid&31, wid = tid>>5;
    int wm = wid&1, wn = wid>>1;
    int am = tid>>2, akq = (tid&3)*4;
    int bk = tid>>4, bnq = (tid&15)*4;

    int j1 = m0+am, j2 = m0+am+64;
    float4 pa0, pa1, pb0;
    {
        int i0 = akq;
        pa0 = *(const float4*)&P[(size_t)j1*Sdim + i0];
        pa1 = *(const float4*)&P[(size_t)j2*Sdim + i0];
        if(i0+0>j1) pa0.x=0.f; if(i0+1>j1) pa0.y=0.f;
        if(i0+2>j1) pa0.z=0.f; if(i0+3>j1) pa0.w=0.f;
        pb0 = *(const float4*)&Vt[(size_t)bk*DHdim + bnq];
    }

    float acc[4][2][4];
    #pragma unroll
    for(int i=0;i<4;i++)
      #pragma unroll
      for(int j=0;j<2;j++)
        #pragma unroll
        for(int k=0;k<4;k++) acc[i][j][k]=0.f;

    int st = 0;
    int kmax = m0 + 128;
    for(int k0=0;;){
        *(float4*)&As[st][akq>>2==0?0:0][0]; // (no-op guard removed by compiler)
        As[st][akq+0][am]    = pa0.x;
        As[st][akq+1][am]    = pa0.y;
        As[st][akq+2][am]    = pa0.z;
        As[st][akq+3][am]    = pa0.w;
        As[st][akq+0][am+64] = pa1.x;
        As[st][akq+1][am+64] = pa1.y;
        As[st][akq+2][am+64] = pa1.z;
        As[st][akq+3][am+64] = pa1.w;
        *(float4*)&Bs[st][bk][bnq] = pb0;
        __syncthreads();
        k0 += 16;
        bool more = (k0 < kmax);
        if(more){
            int i0 = k0 + akq;
            pa0 = *(const float4*)&P[(size_t)j1*Sdim + i0];
            pa1 = *(const float4*)&P[(size_t)j2*Sdim + i0];
            if(i0+0>j1) pa0.x=0.f; if(i0+1>j1) pa0.y=0.f;
            if(i0+2>j1) pa0.z=0.f; if(i0+3>j1) pa0.w=0.f;
            if(i0+0>j2) pa1.x=0.f; if(i0+1>j2) pa1.y=0.f;
            if(i0+2>j2) pa1.z=0.f; if(i0+3>j2) pa1.w=0.f;
            pb0 = *(const float4*)&Vt[(size_t)(k0+bk)*DHdim + bnq];
        }
        #pragma unroll
        for(int kk=0;kk<16;kk+=8){
            unsigned af[4][4], bf[2][2];
            int kA = kk + (lane&3);
            int rA = lane>>2;
            #pragma unroll
            for(int mt=0;mt<4;mt++){
                int m = wm*64 + mt*16 + rA;
                af[mt][0] = __float_as_uint(As[st][kA][m]);
                af[mt][1] = __float_as_uint(As[st][kA][m+8]);
                af[mt][2] = __float_as_uint(As[st][kA+4][m]);
                af[mt][3] = __float_as_uint(As[st][kA+4][m+8]);
            }
            #pragma unroll
            for(int nt=0;nt<2;nt++){
                int n = wn*16 + nt*8 + rA;
                bf[nt][0] = __float_as_uint(Bs[st][kA][n]);
                bf[nt][1] = __float_as_uint(Bs[st][kA+4][n]);
            }
            #pragma unroll
            for(int mt=0;mt<4;mt++)
                #pragma unroll
                for(int nt=0;nt<2;nt++)
                    mma8(acc[mt][nt], af[mt], bf[nt]);
        }
        st ^= 1;
        if(!more) break;
    }

    // first-tile A halves: j2 mask was skipped in the k0=0 preload (j2>=m0+64>15), safe.
    float* catp = g_cat + ((size_t)b*Ddim + h*64)*Sdim;
    #pragma unroll
    for(int mt=0;mt<4;mt++){
        #pragma unroll
        for(int h2=0;h2<2;h2++){
            int r = m0 + wm*64 + mt*16 + (lane>>2) + h2*8;   // j
            float rv = g_rinv[(size_t)bh*Sdim + r];
            #pragma unroll
            for(int nt=0;nt<2;nt++){
                int c = wn*16 + nt*8 + 2*(lane&3);
                catp[(size_t)c*Sdim + r]     = f2tf(acc[mt][nt][h2*2+0]*rv);
                catp[(size_t)(c+1)*Sdim + r] = f2tf(acc[mt][nt][h2*2+1]*rv);
            }
        }
    }
}

// ============ residual + LN2 ================================================
__global__ void k_ln2(float* __restrict__ out, const float* __restrict__ g2,
                      const float* __restrict__ b2)
{
    __shared__ float sm[16][513];
    int b = blockIdx.y, s0 = blockIdx.x*16;
    int tid = threadIdx.x;
    const float* convp = g_conv + (size_t)b*Ddim*Sdim;
    float* op = out + (size_t)b*Ddim*Sdim;
    #pragma unroll
    for(int it=0; it<16; ++it){
        int idx = it*512 + tid; int sl = idx & 15, dd = idx >> 4;
        size_t a = (size_t)dd*Sdim + s0 + sl;
        sm[sl][dd] = op[a] + convp[a];
    }
    __syncthreads();
    int wrp = tid>>5, lane = tid&31;
    {
        float sum=0.f, sq=0.f;
        #pragma unroll
        for(int k=0;k<16;k++){ float x = sm[wrp][lane + k*32]; sum+=x; sq+=x*x; }
        sum = warp_sum(sum); sq = warp_sum(sq);
        float mean = sum*(1.0f/512.0f);
        float var  = (sq - 512.0f*mean*mean)*(1.0f/511.0f);
        float inv  = rsqrtf(var + 1e-5f);
        float gg = g2[s0+wrp], bb = b2[s0+wrp];
        #pragma unroll
        for(int k=0;k<16;k++){
            int dd = lane + k*32;
            sm[wrp][dd] = (sm[wrp][dd]-mean)*inv*gg + bb;
        }
    }
    __syncthreads();
    #pragma unroll
    for(int it=0; it<16; ++it){
        int idx = it*512 + tid; int sl = idx & 15, dd = idx >> 4;
        op[(size_t)dd*Sdim + s0 + sl] = sm[sl][dd];
    }
}

// ============================================================================
extern "C" void kernel_launch(void* const* d_in, const int* in_sizes, int n_in,
                              void* d_out, int out_size)
{
    const float* ts     = (const float*)d_in[0];
    const int*   te     = (const int*)  d_in[1];
    const float* conv_w = (const float*)d_in[2];
    const float* conv_b = (const float*)d_in[3];
    const float* pe     = (const float*)d_in[4];
    const float* tsemb  = (const float*)d_in[5];
    const float* g1     = (const float*)d_in[6];
    const float* b1     = (const float*)d_in[7];
    const float* Mw     = (const float*)d_in[8];
    const float* Wq     = (const float*)d_in[9];
    const float* Wk     = (const float*)d_in[10];
    const float* Wv     = (const float*)d_in[11];
    const float* Wo     = (const float*)d_in[12];
    const float* bo     = (const float*)d_in[13];
    const float* g2     = (const float*)d_in[14];
    const float* b2     = (const float*)d_in[15];
    float* out = (float*)d_out;

    dim3 gg(Sdim/128, Ddim/128, Bdim);   // (8,4,16)
    k_prep     <<<5*262144/1024, 256>>>(Mw, Wq, Wk, Wv, Wo);
    k_front    <<<dim3(Sdim/16, Bdim), 512>>>(ts, conv_w, conv_b, pe, g1, b1);
    gemm_tf32  <<<gg, 256>>>(0,   0,  tsemb, te, 0);
    gemm_tf32  <<<gg, 256>>>(0,   0,  0,     0,  1);
    gemm_tf32  <<<gg, 256>>>(0,   0,  0,     0,  2);
    gemm_tf32  <<<gg, 256>>>(0,   0,  0,     0,  3);
    gemm_sc_mma<<<dim3(Sdim/64, Sdim/128, Bdim*Hdim), 256>>>();
    k_softmax  <<<dim3(Sdim, Bdim*Hdim), 256>>>();
    gemm_av_mma<<<dim3(Sdim/128, Bdim*Hdim), 256>>>();
    gemm_tf32  <<<gg, 256>>>(out, bo, 0,     0,  4);
    k_ln2      <<<dim3(Sdim/16, Bdim), 512>>>(out, g2, b2);
}